// round 6
// baseline (speedup 1.0000x reference)
#include <cuda_runtime.h>
#include <math.h>

// Problem constants (fixed by the dataset)
#define BATCH 8
#define LQ    2048
#define LK    2048
#define DH    128

// Tiling
#define BM 64          // query rows per CTA
#define BN 64          // key rows per inner tile
#define NT 256         // threads per CTA

#define QK_STRIDE (DH + 4)   // 132 floats per row (pad vs bank conflicts)
#define P_STRIDE  (BN + 4)   // 68 floats per row

// smem: Qs[BM][QK_STRIDE] + Ks[BN][QK_STRIDE] + Vs[BN][QK_STRIDE] + Ps[BM][P_STRIDE]
#define SMEM_FLOATS (BM*QK_STRIDE + BN*QK_STRIDE + BN*QK_STRIDE + BM*P_STRIDE)
#define SMEM_BYTES  (SMEM_FLOATS * 4)

__global__ void __launch_bounds__(NT, 1)
attn_scale_kernel(const float* __restrict__ q,
                  const float* __restrict__ k,
                  const float* __restrict__ v,
                  const float* __restrict__ sf,
                  float* __restrict__ out)
{
    extern __shared__ float smem[];
    float* Qs = smem;
    float* Ks = Qs + BM * QK_STRIDE;
    float* Vs = Ks + BN * QK_STRIDE;
    float* Ps = Vs + BN * QK_STRIDE;   // holds scale tile, then P tile

    const int tid = threadIdx.x;
    const int tx  = tid & 15;          // 0..15
    const int ty  = tid >> 4;          // 0..15
    const int qt  = blockIdx.x;        // 0..LQ/BM-1
    const int b   = blockIdx.y;        // 0..BATCH-1
    const int q0  = qt * BM;

    const float* qb = q  + ((size_t)b * LQ + q0) * DH;
    const float* kb = k  + (size_t)b * LK * DH;
    const float* vb = v  + (size_t)b * LK * DH;
    const float* sb = sf + ((size_t)b * LQ + q0) * LK;

    // ---- load Q tile (64 x 128 fp32) ----
    #pragma unroll
    for (int rep = 0; rep < (BM * DH / 4) / NT; rep++) {
        int f  = tid + NT * rep;       // float4 index
        int r  = f >> 5;               // DH/4 = 32 float4 per row
        int c4 = f & 31;
        float4 val = reinterpret_cast<const float4*>(qb + (size_t)r * DH)[c4];
        *reinterpret_cast<float4*>(&Qs[r * QK_STRIDE + c4 * 4]) = val;
    }

    // accumulators: rows ty*4+i ; output cols tx*8+jj
    float o[4][8];
    #pragma unroll
    for (int i = 0; i < 4; i++)
        #pragma unroll
        for (int j = 0; j < 8; j++) o[i][j] = 0.f;

    float rmax[4], rsum[4];
    #pragma unroll
    for (int i = 0; i < 4; i++) { rmax[i] = -INFINITY; rsum[i] = 0.f; }

    for (int kt = 0; kt < LK / BN; kt++) {
        __syncthreads();   // previous iteration done with Ks/Vs/Ps
        const int k0 = kt * BN;

        // ---- load K and V tiles (64 x 128 each) ----
        #pragma unroll
        for (int rep = 0; rep < (BN * DH / 4) / NT; rep++) {
            int f  = tid + NT * rep;
            int r  = f >> 5;
            int c4 = f & 31;
            float4 kv = reinterpret_cast<const float4*>(kb + (size_t)(k0 + r) * DH)[c4];
            *reinterpret_cast<float4*>(&Ks[r * QK_STRIDE + c4 * 4]) = kv;
            float4 vv = reinterpret_cast<const float4*>(vb + (size_t)(k0 + r) * DH)[c4];
            *reinterpret_cast<float4*>(&Vs[r * QK_STRIDE + c4 * 4]) = vv;
        }
        // ---- load scale tile (64 x 64) into Ps ----
        #pragma unroll
        for (int rep = 0; rep < (BM * BN / 4) / NT; rep++) {
            int f  = tid + NT * rep;   // float4 index, 16 per row
            int r  = f >> 4;
            int c4 = f & 15;
            float4 s4 = *reinterpret_cast<const float4*>(sb + (size_t)r * LK + k0 + c4 * 4);
            *reinterpret_cast<float4*>(&Ps[r * P_STRIDE + c4 * 4]) = s4;
        }
        __syncthreads();

        // ---- GEMM1: S[64x64] = Q * K^T ; rows ty*4+i, cols tx+16*j ----
        float acc[4][4];
        #pragma unroll
        for (int i = 0; i < 4; i++)
            #pragma unroll
            for (int j = 0; j < 4; j++) acc[i][j] = 0.f;

        #pragma unroll
        for (int d = 0; d < DH; d += 4) {
            float4 a[4], bb[4];
            #pragma unroll
            for (int i = 0; i < 4; i++)
                a[i] = *reinterpret_cast<const float4*>(&Qs[(ty * 4 + i) * QK_STRIDE + d]);
            #pragma unroll
            for (int j = 0; j < 4; j++)
                bb[j] = *reinterpret_cast<const float4*>(&Ks[(tx + 16 * j) * QK_STRIDE + d]);
            #pragma unroll
            for (int i = 0; i < 4; i++)
                #pragma unroll
                for (int j = 0; j < 4; j++) {
                    acc[i][j] = fmaf(a[i].x, bb[j].x, acc[i][j]);
                    acc[i][j] = fmaf(a[i].y, bb[j].y, acc[i][j]);
                    acc[i][j] = fmaf(a[i].z, bb[j].z, acc[i][j]);
                    acc[i][j] = fmaf(a[i].w, bb[j].w, acc[i][j]);
                }
        }

        // ---- scale, online softmax, write P into Ps (in place over scale) ----
        #pragma unroll
        for (int i = 0; i < 4; i++) {
            const int row = ty * 4 + i;
            float lg[4];
            float lmax = -INFINITY;
            #pragma unroll
            for (int j = 0; j < 4; j++) {
                float s = Ps[row * P_STRIDE + (tx + 16 * j)];
                lg[j] = acc[i][j] * s;
                lmax = fmaxf(lmax, lg[j]);
            }
            // reduce max over the 16 threads covering this row
            #pragma unroll
            for (int off = 1; off < 16; off <<= 1)
                lmax = fmaxf(lmax, __shfl_xor_sync(0xffffffffu, lmax, off));

            float mnew  = fmaxf(rmax[i], lmax);
            float alpha = __expf(rmax[i] - mnew);   // 0 when rmax was -inf
            rmax[i] = mnew;

            float psum = 0.f;
            #pragma unroll
            for (int j = 0; j < 4; j++) {
                float p = __expf(lg[j] - mnew);
                psum += p;
                Ps[row * P_STRIDE + (tx + 16 * j)] = p;
            }
            #pragma unroll
            for (int off = 1; off < 16; off <<= 1)
                psum += __shfl_xor_sync(0xffffffffu, psum, off);

            rsum[i] = rsum[i] * alpha + psum;
            #pragma unroll
            for (int jj = 0; jj < 8; jj++) o[i][jj] *= alpha;
        }
        __syncthreads();   // all P writes visible before GEMM2

        // ---- GEMM2: O += P[64x64] * V[64x128] ; rows ty*4+i, cols tx*8+jj ----
        #pragma unroll
        for (int n = 0; n < BN; n++) {
            float4 v0 = *reinterpret_cast<const float4*>(&Vs[n * QK_STRIDE + tx * 8]);
            float4 v1 = *reinterpret_cast<const float4*>(&Vs[n * QK_STRIDE + tx * 8 + 4]);
            float p[4];
            #pragma unroll
            for (int i = 0; i < 4; i++) p[i] = Ps[(ty * 4 + i) * P_STRIDE + n];
            #pragma unroll
            for (int i = 0; i < 4; i++) {
                o[i][0] = fmaf(p[i], v0.x, o[i][0]);
                o[i][1] = fmaf(p[i], v0.y, o[i][1]);
                o[i][2] = fmaf(p[i], v0.z, o[i][2]);
                o[i][3] = fmaf(p[i], v0.w, o[i][3]);
                o[i][4] = fmaf(p[i], v1.x, o[i][4]);
                o[i][5] = fmaf(p[i], v1.y, o[i][5]);
                o[i][6] = fmaf(p[i], v1.z, o[i][6]);
                o[i][7] = fmaf(p[i], v1.w, o[i][7]);
            }
        }
    }

    // ---- epilogue: normalize and store ----
    float* ob = out + ((size_t)b * LQ + q0) * DH;
    #pragma unroll
    for (int i = 0; i < 4; i++) {
        float inv = 1.f / rsum[i];
        float4 r0, r1;
        r0.x = o[i][0] * inv; r0.y = o[i][1] * inv;
        r0.z = o[i][2] * inv; r0.w = o[i][3] * inv;
        r1.x = o[i][4] * inv; r1.y = o[i][5] * inv;
        r1.z = o[i][6] * inv; r1.w = o[i][7] * inv;
        *reinterpret_cast<float4*>(&ob[(size_t)(ty * 4 + i) * DH + tx * 8])     = r0;
        *reinterpret_cast<float4*>(&ob[(size_t)(ty * 4 + i) * DH + tx * 8 + 4]) = r1;
    }
}

extern "C" void kernel_launch(void* const* d_in, const int* in_sizes, int n_in,
                              void* d_out, int out_size)
{
    const float* q  = (const float*)d_in[0];  // query  [B, LQ, D]
    const float* k  = (const float*)d_in[1];  // key    [B, LK, D]
    const float* v  = (const float*)d_in[2];  // value  [B, LK, D]
    const float* sf = (const float*)d_in[3];  // scale  [B, LQ, LK]
    float* out = (float*)d_out;               // [B, LQ, D]

    cudaFuncSetAttribute(attn_scale_kernel,
                         cudaFuncAttributeMaxDynamicSharedMemorySize, SMEM_BYTES);

    dim3 grid(LQ / BM, BATCH);
    attn_scale_kernel<<<grid, NT, SMEM_BYTES>>>(q, k, v, sf, out);
}

// round 10
// speedup vs baseline: 3.0011x; 3.0011x over previous
#include <cuda_runtime.h>
#include <cuda_bf16.h>
#include <math.h>
#include <stdint.h>

// Problem constants
#define BATCH 8
#define LQ    2048
#define LK    2048
#define DH    128

// Tiling
#define BM 128
#define BN 64
#define NKT (LK / BN)
#define NT  256

// smem rows padded: 128 + 8 bf16 elements -> 272 bytes/row.
// ldmatrix phase: row r starts at word 68r; 68r mod 32 = 4r mod 32 -> conflict-free.
#define SQ 136

#define OFF_QHI 0
#define OFF_QLO (OFF_QHI + BM * SQ * 2)      // 34816
#define OFF_KHI (OFF_QLO + BM * SQ * 2)      // 69632
#define OFF_KLO (OFF_KHI + BN * SQ * 2)      // 87040
#define OFF_VHI (OFF_KLO + BN * SQ * 2)      // 104448
#define OFF_VLO (OFF_VHI + BN * SQ * 2)      // 121856
#define SMEM_BYTES (OFF_VLO + BN * SQ * 2)   // 139264

// ---------------- PTX helpers (base-PTX only: ldmatrix + mma.sync) ----------------
__device__ __forceinline__ uint32_t smem_u32(const void* p) {
    uint32_t a;
    asm("{ .reg .u64 t; cvta.to.shared.u64 t, %1; cvt.u32.u64 %0, t; }"
        : "=r"(a) : "l"(p));
    return a;
}

__device__ __forceinline__ void ldsm_x4(uint32_t& r0, uint32_t& r1,
                                        uint32_t& r2, uint32_t& r3, uint32_t addr) {
    asm volatile("ldmatrix.sync.aligned.m8n8.x4.shared.b16 {%0,%1,%2,%3}, [%4];"
                 : "=r"(r0), "=r"(r1), "=r"(r2), "=r"(r3) : "r"(addr));
}

__device__ __forceinline__ void ldsm_x4_t(uint32_t& r0, uint32_t& r1,
                                          uint32_t& r2, uint32_t& r3, uint32_t addr) {
    asm volatile("ldmatrix.sync.aligned.m8n8.x4.trans.shared.b16 {%0,%1,%2,%3}, [%4];"
                 : "=r"(r0), "=r"(r1), "=r"(r2), "=r"(r3) : "r"(addr));
}

__device__ __forceinline__ void mma16816(float* c,
                                         uint32_t a0, uint32_t a1, uint32_t a2, uint32_t a3,
                                         uint32_t b0, uint32_t b1) {
    asm volatile(
        "mma.sync.aligned.m16n8k16.row.col.f32.bf16.bf16.f32 "
        "{%0,%1,%2,%3}, {%4,%5,%6,%7}, {%8,%9}, {%0,%1,%2,%3};"
        : "+f"(c[0]), "+f"(c[1]), "+f"(c[2]), "+f"(c[3])
        : "r"(a0), "r"(a1), "r"(a2), "r"(a3), "r"(b0), "r"(b1));
}

// bf16 hi/lo split packing
__device__ __forceinline__ uint32_t pack_hi(float x, float y, float& rx, float& ry) {
    __nv_bfloat16 hx = __float2bfloat16(x), hy = __float2bfloat16(y);
    rx = x - __bfloat162float(hx);
    ry = y - __bfloat162float(hy);
    __nv_bfloat162 h; h.x = hx; h.y = hy;
    return *reinterpret_cast<uint32_t*>(&h);
}
__device__ __forceinline__ uint32_t pack_lo(float rx, float ry) {
    __nv_bfloat162 l = __floats2bfloat162_rn(rx, ry);
    return *reinterpret_cast<uint32_t*>(&l);
}
__device__ __forceinline__ void split8(float4 a, float4 c, uint4& hi, uint4& lo) {
    float r0, r1, r2, r3, r4, r5, r6, r7;
    hi.x = pack_hi(a.x, a.y, r0, r1);
    hi.y = pack_hi(a.z, a.w, r2, r3);
    hi.z = pack_hi(c.x, c.y, r4, r5);
    hi.w = pack_hi(c.z, c.w, r6, r7);
    lo.x = pack_lo(r0, r1);
    lo.y = pack_lo(r2, r3);
    lo.z = pack_lo(r4, r5);
    lo.w = pack_lo(r6, r7);
}

// ---------------- kernel ----------------
__global__ void __launch_bounds__(NT, 1)
attn_hmma_kernel(const float* __restrict__ q,
                 const float* __restrict__ k,
                 const float* __restrict__ v,
                 const float* __restrict__ sf,
                 float* __restrict__ out)
{
    extern __shared__ char sm[];
    const uint32_t sb = smem_u32(sm);

    const int tid   = threadIdx.x;
    const int wid   = tid >> 5;
    const int lane  = tid & 31;
    const int g     = lane >> 2;        // group id (row within 8)
    const int tg    = lane & 3;         // thread in group
    const int b     = blockIdx.y;
    const int q0    = blockIdx.x * BM;
    const int rbase = wid * 16;         // this warp's 16 query rows

    const float* qb  = q  + ((size_t)b * LQ + q0) * DH;
    const float* kb  = k  + (size_t)b * LK * DH;
    const float* vb  = v  + (size_t)b * LK * DH;
    const float* sfb = sf + ((size_t)(b * LQ + q0 + rbase + g)) * LK;

    // ldmatrix lane-address components (same formula for A and K-B fragments)
    const uint32_t lrow = (uint32_t)(lane & 15);
    const uint32_t lcol = (uint32_t)((lane & 16) >> 1);   // 0 or 8 elements

    // ---- load + convert Q tile (128 x 128) -> bf16 hi/lo ----
    #pragma unroll
    for (int rep = 0; rep < (BM * DH / 8) / NT; rep++) {
        int f  = tid + NT * rep;
        int r  = f >> 4;
        int c8 = (f & 15) << 3;
        const float* src = qb + (size_t)r * DH + c8;
        float4 a = *reinterpret_cast<const float4*>(src);
        float4 c = *reinterpret_cast<const float4*>(src + 4);
        uint4 hi, lo;
        split8(a, c, hi, lo);
        uint32_t off = ((uint32_t)r * SQ + (uint32_t)c8) * 2u;
        *reinterpret_cast<uint4*>(sm + OFF_QHI + off) = hi;
        *reinterpret_cast<uint4*>(sm + OFF_QLO + off) = lo;
    }

    float o[16][4];
    #pragma unroll
    for (int j = 0; j < 16; j++)
        #pragma unroll
        for (int c = 0; c < 4; c++) o[j][c] = 0.f;

    float rmax_lo = -INFINITY, rmax_hi = -INFINITY;
    float rsum_lo = 0.f, rsum_hi = 0.f;

    #pragma unroll 1
    for (int kt = 0; kt < NKT; kt++) {
        const int k0g = kt * BN;
        __syncthreads();   // previous iteration done reading K/V smem

        // ---- load + convert K and V tiles (64 x 128 each) ----
        #pragma unroll
        for (int rep = 0; rep < (BN * DH / 8) / NT; rep++) {
            int f  = tid + NT * rep;
            int r  = f >> 4;
            int c8 = (f & 15) << 3;
            uint32_t off = ((uint32_t)r * SQ + (uint32_t)c8) * 2u;
            {
                const float* src = kb + (size_t)(k0g + r) * DH + c8;
                float4 a = *reinterpret_cast<const float4*>(src);
                float4 c = *reinterpret_cast<const float4*>(src + 4);
                uint4 hi, lo;
                split8(a, c, hi, lo);
                *reinterpret_cast<uint4*>(sm + OFF_KHI + off) = hi;
                *reinterpret_cast<uint4*>(sm + OFF_KLO + off) = lo;
            }
            {
                const float* src = vb + (size_t)(k0g + r) * DH + c8;
                float4 a = *reinterpret_cast<const float4*>(src);
                float4 c = *reinterpret_cast<const float4*>(src + 4);
                uint4 hi, lo;
                split8(a, c, hi, lo);
                *reinterpret_cast<uint4*>(sm + OFF_VHI + off) = hi;
                *reinterpret_cast<uint4*>(sm + OFF_VLO + off) = lo;
            }
        }
        __syncthreads();

        // ---- GEMM1: S[16 x 64] = Q_w * K^T  (3-term bf16 split) ----
        float s[8][4];
        #pragma unroll
        for (int j = 0; j < 8; j++)
            #pragma unroll
            for (int c = 0; c < 4; c++) s[j][c] = 0.f;

        const uint32_t a_off = (((uint32_t)rbase + lrow) * SQ + lcol) * 2u;
        #pragma unroll
        for (int kk = 0; kk < 8; kk++) {
            const uint32_t koff = (uint32_t)kk * 32u;   // 16 bf16 = 32 bytes
            uint32_t ah0, ah1, ah2, ah3, al0, al1, al2, al3;
            ldsm_x4(ah0, ah1, ah2, ah3, sb + OFF_QHI + a_off + koff);
            ldsm_x4(al0, al1, al2, al3, sb + OFF_QLO + a_off + koff);
            #pragma unroll
            for (int nn = 0; nn < 4; nn++) {
                const uint32_t boff =
                    (((uint32_t)nn * 16u + lrow) * SQ + lcol) * 2u + koff;
                uint32_t bh0, bh1, bh2, bh3, bl0, bl1, bl2, bl3;
                ldsm_x4(bh0, bh1, bh2, bh3, sb + OFF_KHI + boff);
                ldsm_x4(bl0, bl1, bl2, bl3, sb + OFF_KLO + boff);
                mma16816(s[2 * nn],     ah0, ah1, ah2, ah3, bh0, bh2);
                mma16816(s[2 * nn],     ah0, ah1, ah2, ah3, bl0, bl2);
                mma16816(s[2 * nn],     al0, al1, al2, al3, bh0, bh2);
                mma16816(s[2 * nn + 1], ah0, ah1, ah2, ah3, bh1, bh3);
                mma16816(s[2 * nn + 1], ah0, ah1, ah2, ah3, bl1, bl3);
                mma16816(s[2 * nn + 1], al0, al1, al2, al3, bh1, bh3);
            }
        }

        // ---- softmax (thread-local, 2 rows x 16 cols each) ----
        const float* srow = sfb + k0g;
        float mlo = -INFINITY, mhi = -INFINITY;
        #pragma unroll
        for (int j = 0; j < 8; j++) {
            float2 u = __ldg(reinterpret_cast<const float2*>(srow + j * 8 + tg * 2));
            float2 w = __ldg(reinterpret_cast<const float2*>(srow + 8 * LK + j * 8 + tg * 2));
            s[j][0] *= u.x; s[j][1] *= u.y;
            s[j][2] *= w.x; s[j][3] *= w.y;
            mlo = fmaxf(mlo, fmaxf(s[j][0], s[j][1]));
            mhi = fmaxf(mhi, fmaxf(s[j][2], s[j][3]));
        }
        // quad reduce (threads tg=0..3 share a row)
        mlo = fmaxf(mlo, __shfl_xor_sync(0xffffffffu, mlo, 1));
        mlo = fmaxf(mlo, __shfl_xor_sync(0xffffffffu, mlo, 2));
        mhi = fmaxf(mhi, __shfl_xor_sync(0xffffffffu, mhi, 1));
        mhi = fmaxf(mhi, __shfl_xor_sync(0xffffffffu, mhi, 2));

        const float mnew_lo = fmaxf(rmax_lo, mlo);
        const float mnew_hi = fmaxf(rmax_hi, mhi);
        const float alpha_lo = __expf(rmax_lo - mnew_lo);
        const float alpha_hi = __expf(rmax_hi - mnew_hi);
        rmax_lo = mnew_lo; rmax_hi = mnew_hi;

        uint32_t Ph[4][4], Pl[4][4];
        float pslo = 0.f, pshi = 0.f;
        #pragma unroll
        for (int j = 0; j < 8; j++) {
            float p0 = __expf(s[j][0] - mnew_lo);
            float p1 = __expf(s[j][1] - mnew_lo);
            float p2 = __expf(s[j][2] - mnew_hi);
            float p3 = __expf(s[j][3] - mnew_hi);
            pslo += p0 + p1;
            pshi += p2 + p3;
            const int pk = j >> 1;
            const int hf = (j & 1) << 1;
            float r0, r1;
            Ph[pk][hf]     = pack_hi(p0, p1, r0, r1);
            Pl[pk][hf]     = pack_lo(r0, r1);
            Ph[pk][hf + 1] = pack_hi(p2, p3, r0, r1);
            Pl[pk][hf + 1] = pack_lo(r0, r1);
        }
        rsum_lo = rsum_lo * alpha_lo + pslo;
        rsum_hi = rsum_hi * alpha_hi + pshi;
        #pragma unroll
        for (int j = 0; j < 16; j++) {
            o[j][0] *= alpha_lo; o[j][1] *= alpha_lo;
            o[j][2] *= alpha_hi; o[j][3] *= alpha_hi;
        }

        // ---- GEMM2: O += P[16 x 64] * V[64 x 128]  (3-term bf16 split) ----
        #pragma unroll
        for (int pk = 0; pk < 4; pk++) {
            #pragma unroll
            for (int nn = 0; nn < 8; nn++) {
                const uint32_t voff =
                    (((uint32_t)pk * 16u + lrow) * SQ + (uint32_t)nn * 16u + lcol) * 2u;
                uint32_t vh0, vh1, vh2, vh3, vl0, vl1, vl2, vl3;
                ldsm_x4_t(vh0, vh1, vh2, vh3, sb + OFF_VHI + voff);
                ldsm_x4_t(vl0, vl1, vl2, vl3, sb + OFF_VLO + voff);
                mma16816(o[2 * nn],     Ph[pk][0], Ph[pk][1], Ph[pk][2], Ph[pk][3], vh0, vh1);
                mma16816(o[2 * nn],     Ph[pk][0], Ph[pk][1], Ph[pk][2], Ph[pk][3], vl0, vl1);
                mma16816(o[2 * nn],     Pl[pk][0], Pl[pk][1], Pl[pk][2], Pl[pk][3], vh0, vh1);
                mma16816(o[2 * nn + 1], Ph[pk][0], Ph[pk][1], Ph[pk][2], Ph[pk][3], vh2, vh3);
                mma16816(o[2 * nn + 1], Ph[pk][0], Ph[pk][1], Ph[pk][2], Ph[pk][3], vl2, vl3);
                mma16816(o[2 * nn + 1], Pl[pk][0], Pl[pk][1], Pl[pk][2], Pl[pk][3], vh2, vh3);
            }
        }
    }

    // ---- epilogue: reduce row sums over the quad, normalize, store ----
    rsum_lo += __shfl_xor_sync(0xffffffffu, rsum_lo, 1);
    rsum_lo += __shfl_xor_sync(0xffffffffu, rsum_lo, 2);
    rsum_hi += __shfl_xor_sync(0xffffffffu, rsum_hi, 1);
    rsum_hi += __shfl_xor_sync(0xffffffffu, rsum_hi, 2);
    const float inv_lo = 1.f / rsum_lo;
    const float inv_hi = 1.f / rsum_hi;

    float* ob_lo = out + ((size_t)(b * LQ + q0 + rbase + g)) * DH;
    float* ob_hi = ob_lo + 8 * DH;
    #pragma unroll
    for (int j = 0; j < 16; j++) {
        float2 w0, w1;
        w0.x = o[j][0] * inv_lo; w0.y = o[j][1] * inv_lo;
        w1.x = o[j][2] * inv_hi; w1.y = o[j][3] * inv_hi;
        *reinterpret_cast<float2*>(ob_lo + j * 8 + tg * 2) = w0;
        *reinterpret_cast<float2*>(ob_hi + j * 8 + tg * 2) = w1;
    }
}

extern "C" void kernel_launch(void* const* d_in, const int* in_sizes, int n_in,
                              void* d_out, int out_size)
{
    const float* q  = (const float*)d_in[0];
    const float* k  = (const float*)d_in[1];
    const float* v  = (const float*)d_in[2];
    const float* sf = (const float*)d_in[3];
    float* out = (float*)d_out;

    cudaFuncSetAttribute(attn_hmma_kernel,
                         cudaFuncAttributeMaxDynamicSharedMemorySize, SMEM_BYTES);

    dim3 grid(LQ / BM, BATCH);
    attn_hmma_kernel<<<grid, NT, SMEM_BYTES>>>(q, k, v, sf, out);
}

// round 11
// speedup vs baseline: 3.1801x; 1.0596x over previous
#include <cuda_runtime.h>
#include <cuda_bf16.h>
#include <math.h>
#include <stdint.h>

// Problem constants
#define BATCH 8
#define LQ    2048
#define LK    2048
#define DH    128

// Tiling
#define BM 128
#define BN 64
#define NKT (LK / BN)
#define NT  256

// smem rows padded: 128 + 8 bf16 elements -> 272 bytes/row.
// ldmatrix phase: row r starts at word 68r; 68r mod 32 = 4r mod 32 -> conflict-free.
#define SQ 136

#define OFF_QHI 0
#define OFF_QLO 34816
#define ST_SIZE 69632                       // one K/V stage: 4 x 17408
#define OFF_ST(s)     (69632 + (s) * ST_SIZE)
#define OFF_KHI_ST(s) (OFF_ST(s))
#define OFF_KLO_ST(s) (OFF_ST(s) + 17408)
#define OFF_VHI_ST(s) (OFF_ST(s) + 34816)
#define OFF_VLO_ST(s) (OFF_ST(s) + 52224)
#define SMEM_BYTES    (69632 + 2 * ST_SIZE)  // 208896

// ---------------- device-global bf16 hi/lo scratch (preconverted Q/K/V) ----------------
#define NEL (BATCH * 2048 * 128)
__device__ __nv_bfloat16 g_qhi[NEL];
__device__ __nv_bfloat16 g_qlo[NEL];
__device__ __nv_bfloat16 g_khi[NEL];
__device__ __nv_bfloat16 g_klo[NEL];
__device__ __nv_bfloat16 g_vhi[NEL];
__device__ __nv_bfloat16 g_vlo[NEL];

// ---------------- PTX helpers (base-PTX only) ----------------
__device__ __forceinline__ uint32_t smem_u32(const void* p) {
    uint32_t a;
    asm("{ .reg .u64 t; cvta.to.shared.u64 t, %1; cvt.u32.u64 %0, t; }"
        : "=r"(a) : "l"(p));
    return a;
}

__device__ __forceinline__ void cpa16(uint32_t dst, const void* src) {
    asm volatile("cp.async.cg.shared.global [%0], [%1], 16;"
                 :: "r"(dst), "l"(src) : "memory");
}
#define CP_COMMIT() asm volatile("cp.async.commit_group;" ::: "memory")
#define CP_WAIT(n)  asm volatile("cp.async.wait_group %0;" :: "n"(n) : "memory")

__device__ __forceinline__ void ldsm_x4(uint32_t& r0, uint32_t& r1,
                                        uint32_t& r2, uint32_t& r3, uint32_t addr) {
    asm volatile("ldmatrix.sync.aligned.m8n8.x4.shared.b16 {%0,%1,%2,%3}, [%4];"
                 : "=r"(r0), "=r"(r1), "=r"(r2), "=r"(r3) : "r"(addr));
}
__device__ __forceinline__ void ldsm_x4_t(uint32_t& r0, uint32_t& r1,
                                          uint32_t& r2, uint32_t& r3, uint32_t addr) {
    asm volatile("ldmatrix.sync.aligned.m8n8.x4.trans.shared.b16 {%0,%1,%2,%3}, [%4];"
                 : "=r"(r0), "=r"(r1), "=r"(r2), "=r"(r3) : "r"(addr));
}
__device__ __forceinline__ void mma16816(float* c,
                                         uint32_t a0, uint32_t a1, uint32_t a2, uint32_t a3,
                                         uint32_t b0, uint32_t b1) {
    asm volatile(
        "mma.sync.aligned.m16n8k16.row.col.f32.bf16.bf16.f32 "
        "{%0,%1,%2,%3}, {%4,%5,%6,%7}, {%8,%9}, {%0,%1,%2,%3};"
        : "+f"(c[0]), "+f"(c[1]), "+f"(c[2]), "+f"(c[3])
        : "r"(a0), "r"(a1), "r"(a2), "r"(a3), "r"(b0), "r"(b1));
}

// bf16 hi/lo split packing
__device__ __forceinline__ uint32_t pack_hi(float x, float y, float& rx, float& ry) {
    __nv_bfloat16 hx = __float2bfloat16(x), hy = __float2bfloat16(y);
    rx = x - __bfloat162float(hx);
    ry = y - __bfloat162float(hy);
    __nv_bfloat162 h; h.x = hx; h.y = hy;
    return *reinterpret_cast<uint32_t*>(&h);
}
__device__ __forceinline__ uint32_t pack_lo(float rx, float ry) {
    __nv_bfloat162 l = __floats2bfloat162_rn(rx, ry);
    return *reinterpret_cast<uint32_t*>(&l);
}

// ---------------- preprocessing: fp32 -> bf16 hi/lo for Q, K, V ----------------
#define N4 (NEL / 4)

__global__ void __launch_bounds__(256)
preprocess_kernel(const float* __restrict__ q,
                  const float* __restrict__ k,
                  const float* __restrict__ v)
{
    size_t i = (size_t)blockIdx.x * blockDim.x + threadIdx.x;   // float4 index
    const float* src;
    __nv_bfloat16 *hi, *lo;
    size_t j;
    if (i < (size_t)N4)            { j = i;              src = q; hi = g_qhi; lo = g_qlo; }
    else if (i < (size_t)2 * N4)   { j = i - N4;         src = k; hi = g_khi; lo = g_klo; }
    else                           { j = i - 2 * (size_t)N4; src = v; hi = g_vhi; lo = g_vlo; }

    float4 a = reinterpret_cast<const float4*>(src)[j];
    float r0, r1, r2, r3;
    uint32_t h0 = pack_hi(a.x, a.y, r0, r1);
    uint32_t h1 = pack_hi(a.z, a.w, r2, r3);
    uint32_t l0 = pack_lo(r0, r1);
    uint32_t l1 = pack_lo(r2, r3);
    reinterpret_cast<uint2*>(hi)[j] = make_uint2(h0, h1);
    reinterpret_cast<uint2*>(lo)[j] = make_uint2(l0, l1);
}

// ---------------- main kernel ----------------
__device__ __forceinline__ void load_kv_tile(uint32_t sb, int b, int k0g, int st, int tid) {
    const uint32_t kh = sb + OFF_KHI_ST(st);
    const uint32_t kl = sb + OFF_KLO_ST(st);
    const uint32_t vh = sb + OFF_VHI_ST(st);
    const uint32_t vl = sb + OFF_VLO_ST(st);
    #pragma unroll
    for (int rep = 0; rep < (BN * DH / 8) / NT; rep++) {   // 4 reps
        int f  = tid + NT * rep;
        int r  = f >> 4;
        int c8 = (f & 15) << 3;
        size_t gi = ((size_t)b * LK + (size_t)(k0g + r)) * DH + c8;
        uint32_t off = ((uint32_t)r * SQ + (uint32_t)c8) * 2u;
        cpa16(kh + off, g_khi + gi);
        cpa16(kl + off, g_klo + gi);
        cpa16(vh + off, g_vhi + gi);
        cpa16(vl + off, g_vlo + gi);
    }
}

__global__ void __launch_bounds__(NT, 1)
attn_hmma_kernel(const float* __restrict__ sf,
                 float* __restrict__ out)
{
    extern __shared__ char sm[];
    const uint32_t sb = smem_u32(sm);

    const int tid   = threadIdx.x;
    const int wid   = tid >> 5;
    const int lane  = tid & 31;
    const int g     = lane >> 2;
    const int tg    = lane & 3;
    const int b     = blockIdx.y;
    const int q0    = blockIdx.x * BM;
    const int rbase = wid * 16;

    const float* sfb = sf + ((size_t)(b * LQ + q0 + rbase + g)) * LK;

    const uint32_t lrow = (uint32_t)(lane & 15);
    const uint32_t lcol = (uint32_t)((lane & 16) >> 1);

    // ---- prologue: async-load Q (bf16 hi/lo) and K/V tile 0 ----
    #pragma unroll
    for (int rep = 0; rep < (BM * DH / 8) / NT; rep++) {   // 8 reps
        int f  = tid + NT * rep;
        int r  = f >> 4;
        int c8 = (f & 15) << 3;
        size_t gi = ((size_t)b * LQ + (size_t)(q0 + r)) * DH + c8;
        uint32_t off = ((uint32_t)r * SQ + (uint32_t)c8) * 2u;
        cpa16(sb + OFF_QHI + off, g_qhi + gi);
        cpa16(sb + OFF_QLO + off, g_qlo + gi);
    }
    load_kv_tile(sb, b, 0, 0, tid);
    CP_COMMIT();

    float o[16][4];
    #pragma unroll
    for (int j = 0; j < 16; j++)
        #pragma unroll
        for (int c = 0; c < 4; c++) o[j][c] = 0.f;

    float rmax_lo = -INFINITY, rmax_hi = -INFINITY;
    float rsum_lo = 0.f, rsum_hi = 0.f;

    #pragma unroll 1
    for (int kt = 0; kt < NKT; kt++) {
        const int k0g = kt * BN;
        const int st  = kt & 1;

        // issue next tile into the other stage, then wait for current tile
        if (kt + 1 < NKT) {
            load_kv_tile(sb, b, k0g + BN, st ^ 1, tid);
            CP_COMMIT();
            CP_WAIT(1);
        } else {
            CP_WAIT(0);
        }
        __syncthreads();   // current-stage data visible to all warps

        const uint32_t khb = sb + OFF_KHI_ST(st);
        const uint32_t klb = sb + OFF_KLO_ST(st);
        const uint32_t vhb = sb + OFF_VHI_ST(st);
        const uint32_t vlb = sb + OFF_VLO_ST(st);

        // ---- prefetch scale_factor rows into registers (hide behind GEMM1) ----
        const float* srow = sfb + k0g;
        float2 sfr0[8], sfr1[8];
        #pragma unroll
        for (int j = 0; j < 8; j++) {
            sfr0[j] = __ldg(reinterpret_cast<const float2*>(srow + j * 8 + tg * 2));
            sfr1[j] = __ldg(reinterpret_cast<const float2*>(srow + 8 * LK + j * 8 + tg * 2));
        }

        // ---- GEMM1: S[16 x 64] = Q_w * K^T  (3-term bf16 split) ----
        float s[8][4];
        #pragma unroll
        for (int j = 0; j < 8; j++)
            #pragma unroll
            for (int c = 0; c < 4; c++) s[j][c] = 0.f;

        const uint32_t a_off = (((uint32_t)rbase + lrow) * SQ + lcol) * 2u;
        #pragma unroll
        for (int kk = 0; kk < 8; kk++) {
            const uint32_t koff = (uint32_t)kk * 32u;
            uint32_t ah0, ah1, ah2, ah3, al0, al1, al2, al3;
            ldsm_x4(ah0, ah1, ah2, ah3, sb + OFF_QHI + a_off + koff);
            ldsm_x4(al0, al1, al2, al3, sb + OFF_QLO + a_off + koff);
            #pragma unroll
            for (int nn = 0; nn < 4; nn++) {
                const uint32_t boff =
                    (((uint32_t)nn * 16u + lrow) * SQ + lcol) * 2u + koff;
                uint32_t bh0, bh1, bh2, bh3, bl0, bl1, bl2, bl3;
                ldsm_x4(bh0, bh1, bh2, bh3, khb + boff);
                ldsm_x4(bl0, bl1, bl2, bl3, klb + boff);
                mma16816(s[2 * nn],     ah0, ah1, ah2, ah3, bh0, bh2);
                mma16816(s[2 * nn],     ah0, ah1, ah2, ah3, bl0, bl2);
                mma16816(s[2 * nn],     al0, al1, al2, al3, bh0, bh2);
                mma16816(s[2 * nn + 1], ah0, ah1, ah2, ah3, bh1, bh3);
                mma16816(s[2 * nn + 1], ah0, ah1, ah2, ah3, bl1, bl3);
                mma16816(s[2 * nn + 1], al0, al1, al2, al3, bh1, bh3);
            }
        }

        // ---- softmax (thread-local, 2 rows x 16 cols each) ----
        float mlo = -INFINITY, mhi = -INFINITY;
        #pragma unroll
        for (int j = 0; j < 8; j++) {
            s[j][0] *= sfr0[j].x; s[j][1] *= sfr0[j].y;
            s[j][2] *= sfr1[j].x; s[j][3] *= sfr1[j].y;
            mlo = fmaxf(mlo, fmaxf(s[j][0], s[j][1]));
            mhi = fmaxf(mhi, fmaxf(s[j][2], s[j][3]));
        }
        mlo = fmaxf(mlo, __shfl_xor_sync(0xffffffffu, mlo, 1));
        mlo = fmaxf(mlo, __shfl_xor_sync(0xffffffffu, mlo, 2));
        mhi = fmaxf(mhi, __shfl_xor_sync(0xffffffffu, mhi, 1));
        mhi = fmaxf(mhi, __shfl_xor_sync(0xffffffffu, mhi, 2));

        const float mnew_lo = fmaxf(rmax_lo, mlo);
        const float mnew_hi = fmaxf(rmax_hi, mhi);
        const float alpha_lo = __expf(rmax_lo - mnew_lo);
        const float alpha_hi = __expf(rmax_hi - mnew_hi);
        rmax_lo = mnew_lo; rmax_hi = mnew_hi;

        uint32_t Ph[4][4], Pl[4][4];
        float pslo = 0.f, pshi = 0.f;
        #pragma unroll
        for (int j = 0; j < 8; j++) {
            float p0 = __expf(s[j][0] - mnew_lo);
            float p1 = __expf(s[j][1] - mnew_lo);
            float p2 = __expf(s[j][2] - mnew_hi);
            float p3 = __expf(s[j][3] - mnew_hi);
            pslo += p0 + p1;
            pshi += p2 + p3;
            const int pk = j >> 1;
            const int hf = (j & 1) << 1;
            float r0, r1;
            Ph[pk][hf]     = pack_hi(p0, p1, r0, r1);
            Pl[pk][hf]     = pack_lo(r0, r1);
            Ph[pk][hf + 1] = pack_hi(p2, p3, r0, r1);
            Pl[pk][hf + 1] = pack_lo(r0, r1);
        }
        rsum_lo = rsum_lo * alpha_lo + pslo;
        rsum_hi = rsum_hi * alpha_hi + pshi;
        #pragma unroll
        for (int j = 0; j < 16; j++) {
            o[j][0] *= alpha_lo; o[j][1] *= alpha_lo;
            o[j][2] *= alpha_hi; o[j][3] *= alpha_hi;
        }

        // ---- GEMM2: O += P[16 x 64] * V[64 x 128]  (3-term bf16 split) ----
        #pragma unroll
        for (int pk = 0; pk < 4; pk++) {
            #pragma unroll
            for (int nn = 0; nn < 8; nn++) {
                const uint32_t voff =
                    (((uint32_t)pk * 16u + lrow) * SQ + (uint32_t)nn * 16u + lcol) * 2u;
                uint32_t vh0, vh1, vh2, vh3, vl0, vl1, vl2, vl3;
                ldsm_x4_t(vh0, vh1, vh2, vh3, vhb + voff);
                ldsm_x4_t(vl0, vl1, vl2, vl3, vlb + voff);
                mma16816(o[2 * nn],     Ph[pk][0], Ph[pk][1], Ph[pk][2], Ph[pk][3], vh0, vh1);
                mma16816(o[2 * nn],     Ph[pk][0], Ph[pk][1], Ph[pk][2], Ph[pk][3], vl0, vl1);
                mma16816(o[2 * nn],     Pl[pk][0], Pl[pk][1], Pl[pk][2], Pl[pk][3], vh0, vh1);
                mma16816(o[2 * nn + 1], Ph[pk][0], Ph[pk][1], Ph[pk][2], Ph[pk][3], vh2, vh3);
                mma16816(o[2 * nn + 1], Ph[pk][0], Ph[pk][1], Ph[pk][2], Ph[pk][3], vl2, vl3);
                mma16816(o[2 * nn + 1], Pl[pk][0], Pl[pk][1], Pl[pk][2], Pl[pk][3], vh2, vh3);
            }
        }
        __syncthreads();   // all warps done reading stage st before it is overwritten
    }

    // ---- epilogue: reduce row sums over the quad, normalize, store ----
    rsum_lo += __shfl_xor_sync(0xffffffffu, rsum_lo, 1);
    rsum_lo += __shfl_xor_sync(0xffffffffu, rsum_lo, 2);
    rsum_hi += __shfl_xor_sync(0xffffffffu, rsum_hi, 1);
    rsum_hi += __shfl_xor_sync(0xffffffffu, rsum_hi, 2);
    const float inv_lo = 1.f / rsum_lo;
    const float inv_hi = 1.f / rsum_hi;

    float* ob_lo = out + ((size_t)(b * LQ + q0 + rbase + g)) * DH;
    float* ob_hi = ob_lo + 8 * DH;
    #pragma unroll
    for (int j = 0; j < 16; j++) {
        float2 w0, w1;
        w0.x = o[j][0] * inv_lo; w0.y = o[j][1] * inv_lo;
        w1.x = o[j][2] * inv_hi; w1.y = o[j][3] * inv_hi;
        *reinterpret_cast<float2*>(ob_lo + j * 8 + tg * 2) = w0;
        *reinterpret_cast<float2*>(ob_hi + j * 8 + tg * 2) = w1;
    }
}

extern "C" void kernel_launch(void* const* d_in, const int* in_sizes, int n_in,
                              void* d_out, int out_size)
{
    const float* q  = (const float*)d_in[0];
    const float* k  = (const float*)d_in[1];
    const float* v  = (const float*)d_in[2];
    const float* sf = (const float*)d_in[3];
    float* out = (float*)d_out;

    // 1) convert Q/K/V to bf16 hi/lo scratch
    preprocess_kernel<<<(3 * N4) / 256, 256>>>(q, k, v);

    // 2) attention
    cudaFuncSetAttribute(attn_hmma_kernel,
                         cudaFuncAttributeMaxDynamicSharedMemorySize, SMEM_BYTES);
    dim3 grid(LQ / BM, BATCH);
    attn_hmma_kernel<<<grid, NT, SMEM_BYTES>>>(sf, out);
}